// round 3
// baseline (speedup 1.0000x reference)
#include <cuda_runtime.h>
#include <math.h>

// Problem constants (fixed shapes)
#define N_NODES 32768
#define N_EDGES 16384
#define DEG 4          // edges per node
#define EK 8           // nodes per edge
#define L_KEYS 32      // DEG*EK
#define IN_DIM 128
#define OUT_DIM 128
#define EDGE_DIM 64
#define NUM_HEADS 8
#define HEAD_DIM 16    // OUT_DIM/NUM_HEADS

// ---------------- device scratch (allocation-free rule: __device__ globals) ----
__device__ float g_Wcat[384 * 128];     // [WqL;WkL;WvL] rows x IN_DIM
__device__ float g_WkE[128 * 64];       // Wk @ W_edge
__device__ float g_bias_cat[384];       // bq | 0 | 0
__device__ float g_QKV[(size_t)N_NODES * 384];   // per node: Q[0:128) K[128:256) V[256:384)
__device__ float g_Ke[(size_t)N_EDGES * 128];    // per-edge key bias (incl. bk)
__device__ float g_ctx[(size_t)N_NODES * 128];   // attention context

// ---------------- kernel 1: fuse weight products -------------------------------
// WqL[r,i] = sum_o Wq[r,o]*W_lin[o,i]  (same for Wk, Wv) ; WkE[r,i] = sum_o Wk[r,o]*W_edge[o,i]
__global__ void prep_kernel(const float* __restrict__ Wlin, const float* __restrict__ Wedge,
                            const float* __restrict__ Wq, const float* __restrict__ Wk,
                            const float* __restrict__ Wv, const float* __restrict__ bq) {
    int idx = blockIdx.x * 256 + threadIdx.x;
    if (idx < 384) g_bias_cat[idx] = (idx < 128) ? bq[idx] : 0.0f;
    if (idx < 384 * 128) {
        int o = idx >> 7;          // output row in concat (0..383)
        int i = idx & 127;         // input col
        const float* W = (o < 128) ? Wq : (o < 256) ? Wk : Wv;
        int r = o & 127;
        float s = 0.0f;
        #pragma unroll 8
        for (int c = 0; c < 128; ++c) s += W[r * 128 + c] * Wlin[c * 128 + i];
        g_Wcat[idx] = s;
    } else {
        int j = idx - 384 * 128;
        if (j < 128 * 64) {
            int r = j >> 6;
            int i = j & 63;
            float s = 0.0f;
            #pragma unroll 8
            for (int c = 0; c < 128; ++c) s += Wk[r * 128 + c] * Wedge[c * 64 + i];
            g_WkE[j] = s;
        }
    }
}

// ---------------- generic NT SGEMM: C[M,N] = A[M,K] * B[N,K]^T + bias[col] ------
// BM=BN=128, BK=16, 256 threads, 8x8 microtile.  M%128==0, N%128==0, K%16==0.
template <bool RELU>
__global__ __launch_bounds__(256, 2)
void sgemm_nt(const float* __restrict__ A, const float* __restrict__ B,
              const float* __restrict__ bias, float* __restrict__ C,
              int M, int N, int K) {
    const int BM = 128, BN = 128, BK = 16;
    __shared__ float As[BK][BM];
    __shared__ float Bs[BK][BN];
    const int tid = threadIdx.x;
    const int tx = tid & 15;      // 0..15 -> col group
    const int ty = tid >> 4;      // 0..15 -> row group
    const int brow = blockIdx.x * BM;
    const int bcol = blockIdx.y * BN;

    float acc[8][8];
    #pragma unroll
    for (int i = 0; i < 8; ++i)
        #pragma unroll
        for (int j = 0; j < 8; ++j) acc[i][j] = 0.0f;

    for (int k0 = 0; k0 < K; k0 += BK) {
        // load A tile: 128x16 = 512 float4, 2 per thread
        #pragma unroll
        for (int i = 0; i < 2; ++i) {
            int t = tid + i * 256;
            int r = t >> 2;          // row 0..127
            int c = t & 3;           // float4 within k-slab
            float4 v = *(const float4*)&A[(size_t)(brow + r) * K + k0 + c * 4];
            As[c * 4 + 0][r] = v.x; As[c * 4 + 1][r] = v.y;
            As[c * 4 + 2][r] = v.z; As[c * 4 + 3][r] = v.w;
        }
        #pragma unroll
        for (int i = 0; i < 2; ++i) {
            int t = tid + i * 256;
            int r = t >> 2;
            int c = t & 3;
            float4 v = *(const float4*)&B[(size_t)(bcol + r) * K + k0 + c * 4];
            Bs[c * 4 + 0][r] = v.x; Bs[c * 4 + 1][r] = v.y;
            Bs[c * 4 + 2][r] = v.z; Bs[c * 4 + 3][r] = v.w;
        }
        __syncthreads();
        #pragma unroll
        for (int kk = 0; kk < BK; ++kk) {
            float a[8], b[8];
            *(float4*)&a[0] = *(const float4*)&As[kk][ty * 8];
            *(float4*)&a[4] = *(const float4*)&As[kk][ty * 8 + 4];
            *(float4*)&b[0] = *(const float4*)&Bs[kk][tx * 8];
            *(float4*)&b[4] = *(const float4*)&Bs[kk][tx * 8 + 4];
            #pragma unroll
            for (int i = 0; i < 8; ++i)
                #pragma unroll
                for (int j = 0; j < 8; ++j) acc[i][j] += a[i] * b[j];
        }
        __syncthreads();
    }

    #pragma unroll
    for (int i = 0; i < 8; ++i) {
        int row = brow + ty * 8 + i;
        #pragma unroll
        for (int j = 0; j < 8; j += 4) {
            int col = bcol + tx * 8 + j;
            float4 o;
            o.x = acc[i][j + 0] + bias[col + 0];
            o.y = acc[i][j + 1] + bias[col + 1];
            o.z = acc[i][j + 2] + bias[col + 2];
            o.w = acc[i][j + 3] + bias[col + 3];
            if (RELU) {
                o.x = fmaxf(o.x, 0.0f); o.y = fmaxf(o.y, 0.0f);
                o.z = fmaxf(o.z, 0.0f); o.w = fmaxf(o.w, 0.0f);
            }
            *(float4*)&C[(size_t)row * N + col] = o;
        }
    }
}

// ---------------- kernel 4: gather + multi-head attention (warp per node) ------
__global__ __launch_bounds__(256)
void attn_kernel(const int* __restrict__ node_edges, const int* __restrict__ edge_nodes,
                 const float* __restrict__ bv) {
    __shared__ float s_attn[8][8][33];   // [warp][head][l], padded vs bank conflicts
    const unsigned FULL = 0xffffffffu;
    const int warp = threadIdx.x >> 5;
    const int lane = threadIdx.x & 31;
    const int n = blockIdx.x * 8 + warp;

    // per-lane slice of q: dims 4*lane .. 4*lane+3  (head = lane/4)
    float4 q4 = *(const float4*)&g_QKV[(size_t)n * 384 + lane * 4];

    // edges of this node; lane d (0..3) holds e[d]
    int e_mine = node_edges[n * DEG + (lane & 3)];
    // key slot for THIS lane: l = lane, d = lane>>3, k = lane&7
    int e_l = __shfl_sync(FULL, e_mine, lane >> 3);
    int u   = edge_nodes[e_l * EK + (lane & 7)];

    // ---- phase 1: scores[h][l] = q_h . (Kh[u_l] + Ke[e_l])_h * 0.25
    #pragma unroll
    for (int l = 0; l < L_KEYS; ++l) {
        int uu = __shfl_sync(FULL, u,   l);
        int ee = __shfl_sync(FULL, e_l, l);
        float4 kv = *(const float4*)&g_QKV[(size_t)uu * 384 + 128 + lane * 4];
        float4 ke = *(const float4*)&g_Ke[(size_t)ee * 128 + lane * 4];
        float p = q4.x * (kv.x + ke.x) + q4.y * (kv.y + ke.y)
                + q4.z * (kv.z + ke.z) + q4.w * (kv.w + ke.w);
        // reduce the 4 lanes of a head
        p += __shfl_xor_sync(FULL, p, 1);
        p += __shfl_xor_sync(FULL, p, 2);
        if ((lane & 3) == 0) s_attn[warp][lane >> 2][l] = p * 0.25f;  // 1/sqrt(16)
    }
    __syncwarp();

    // ---- phase 2: softmax over L per head (lanes 0..7)
    if (lane < 8) {
        float m = -INFINITY;
        #pragma unroll
        for (int l = 0; l < L_KEYS; ++l) m = fmaxf(m, s_attn[warp][lane][l]);
        float s = 0.0f;
        #pragma unroll
        for (int l = 0; l < L_KEYS; ++l) {
            float ex = __expf(s_attn[warp][lane][l] - m);
            s_attn[warp][lane][l] = ex;
            s += ex;
        }
        float inv = 1.0f / s;
        #pragma unroll
        for (int l = 0; l < L_KEYS; ++l) s_attn[warp][lane][l] *= inv;
    }
    __syncwarp();

    // ---- phase 3: ctx = sum_l attn[h][l] * Vh[u_l]  (+ bv, since sum attn = 1)
    float4 acc = make_float4(0.f, 0.f, 0.f, 0.f);
    const int h = lane >> 2;
    #pragma unroll
    for (int l = 0; l < L_KEYS; ++l) {
        int uu = __shfl_sync(FULL, u, l);
        float a = s_attn[warp][h][l];
        float4 vv = *(const float4*)&g_QKV[(size_t)uu * 384 + 256 + lane * 4];
        acc.x += a * vv.x; acc.y += a * vv.y;
        acc.z += a * vv.z; acc.w += a * vv.w;
    }
    float4 b4 = *(const float4*)&bv[lane * 4];
    acc.x += b4.x; acc.y += b4.y; acc.z += b4.z; acc.w += b4.w;
    *(float4*)&g_ctx[(size_t)n * 128 + lane * 4] = acc;
}

// ---------------- launch --------------------------------------------------------
extern "C" void kernel_launch(void* const* d_in, const int* in_sizes, int n_in,
                              void* d_out, int out_size) {
    const float* x          = (const float*)d_in[0];
    const float* edge_attr  = (const float*)d_in[1];
    const int*   node_edges = (const int*)  d_in[2];
    const int*   edge_nodes = (const int*)  d_in[3];
    const float* W_lin      = (const float*)d_in[4];
    const float* W_edge     = (const float*)d_in[5];
    const float* Wq         = (const float*)d_in[6];
    const float* Wk         = (const float*)d_in[7];
    const float* Wv         = (const float*)d_in[8];
    const float* bq         = (const float*)d_in[9];
    const float* bk         = (const float*)d_in[10];
    const float* bv         = (const float*)d_in[11];
    const float* Wo         = (const float*)d_in[12];
    const float* bo         = (const float*)d_in[13];
    float* out = (float*)d_out;

    float *pWcat, *pWkE, *pbias, *pQKV, *pKe, *pctx;
    cudaGetSymbolAddress((void**)&pWcat, g_Wcat);
    cudaGetSymbolAddress((void**)&pWkE,  g_WkE);
    cudaGetSymbolAddress((void**)&pbias, g_bias_cat);
    cudaGetSymbolAddress((void**)&pQKV,  g_QKV);
    cudaGetSymbolAddress((void**)&pKe,   g_Ke);
    cudaGetSymbolAddress((void**)&pctx,  g_ctx);

    // 1) fuse weights: Wcat = [Wq;Wk;Wv] @ W_lin ; WkE = Wk @ W_edge ; bias_cat
    prep_kernel<<<224, 256>>>(W_lin, W_edge, Wq, Wk, Wv, bq);

    // 2) QKV = x @ Wcat^T + [bq|0|0]      [32768, 384]
    sgemm_nt<false><<<dim3(N_NODES / 128, 3), 256>>>(x, pWcat, pbias, pQKV,
                                                     N_NODES, 384, IN_DIM);

    // 3) Ke = edge_attr @ WkE^T + bk      [16384, 128]
    sgemm_nt<false><<<dim3(N_EDGES / 128, 1), 256>>>(edge_attr, pWkE, bk, pKe,
                                                     N_EDGES, 128, EDGE_DIM);

    // 4) gather + attention -> ctx        [32768, 128]
    attn_kernel<<<N_NODES / 8, 256>>>(node_edges, edge_nodes, bv);

    // 5) out = relu(ctx @ Wo^T + bo)      [32768, 128]
    sgemm_nt<true><<<dim3(N_NODES / 128, 1), 256>>>(pctx, Wo, bo, out,
                                                    N_NODES, OUT_DIM, OUT_DIM);
}

// round 4
// speedup vs baseline: 1.7047x; 1.7047x over previous
#include <cuda_runtime.h>
#include <math.h>

// Problem constants (fixed shapes)
#define N_NODES 32768
#define N_EDGES 16384
#define DEG 4          // edges per node
#define EK 8           // nodes per edge
#define L_KEYS 32      // DEG*EK
#define IN_DIM 128
#define OUT_DIM 128
#define EDGE_DIM 64
#define NUM_HEADS 8
#define HEAD_DIM 16    // OUT_DIM/NUM_HEADS

// ---------------- device scratch (allocation-free rule: __device__ globals) ----
__device__ float g_Wcat[384 * 128];     // [WqL;WkL;WvL] rows x IN_DIM
__device__ float g_WkE[128 * 64];       // Wk @ W_edge
__device__ float g_bias_cat[384];       // bq | 0 | 0
__device__ float g_QKV[(size_t)N_NODES * 384];   // per node: Q[0:128) K[128:256) V[256:384)
__device__ float g_Ke[(size_t)N_EDGES * 128];    // per-edge key bias (incl. bk)
__device__ float g_ctx[(size_t)N_NODES * 128];   // attention context

// ---------------- kernel 1: fuse weight products -------------------------------
__global__ void prep_kernel(const float* __restrict__ Wlin, const float* __restrict__ Wedge,
                            const float* __restrict__ Wq, const float* __restrict__ Wk,
                            const float* __restrict__ Wv, const float* __restrict__ bq) {
    int idx = blockIdx.x * 256 + threadIdx.x;
    if (idx < 384) g_bias_cat[idx] = (idx < 128) ? bq[idx] : 0.0f;
    if (idx < 384 * 128) {
        int o = idx >> 7;          // output row in concat (0..383)
        int i = idx & 127;         // input col
        const float* W = (o < 128) ? Wq : (o < 256) ? Wk : Wv;
        int r = o & 127;
        float s = 0.0f;
        #pragma unroll 8
        for (int c = 0; c < 128; ++c) s += W[r * 128 + c] * Wlin[c * 128 + i];
        g_Wcat[idx] = s;
    } else {
        int j = idx - 384 * 128;
        if (j < 128 * 64) {
            int r = j >> 6;
            int i = j & 63;
            float s = 0.0f;
            #pragma unroll 8
            for (int c = 0; c < 128; ++c) s += Wk[r * 128 + c] * Wedge[c * 64 + i];
            g_WkE[j] = s;
        }
    }
}

// ---------------- NT SGEMM with register-prefetch double buffering --------------
// C[M,N] = A[M,K] * B[N,K]^T + bias[col].  BM=BN=128, BK=16, 256 thr, 8x8 micro.
template <bool RELU>
__global__ __launch_bounds__(256, 2)
void sgemm_nt(const float* __restrict__ A, const float* __restrict__ B,
              const float* __restrict__ bias, float* __restrict__ C,
              int M, int N, int K) {
    const int BK = 16;
    __shared__ float As[BK][128];
    __shared__ float Bs[BK][128];
    const int tid = threadIdx.x;
    const int tx = tid & 15;      // 0..15 -> col group
    const int ty = tid >> 4;      // 0..15 -> row group
    const int brow = blockIdx.x * 128;
    const int bcol = blockIdx.y * 128;

    const int lr = tid >> 2;      // row within tile for loads (0..63, +64 for i=1)
    const int lc = tid & 3;       // float4 slot within the 16-wide k slab

    float acc[8][8];
    #pragma unroll
    for (int i = 0; i < 8; ++i)
        #pragma unroll
        for (int j = 0; j < 8; ++j) acc[i][j] = 0.0f;

    // prefetch first tile into registers
    float4 pa[2], pb[2];
    #pragma unroll
    for (int i = 0; i < 2; ++i) {
        pa[i] = *(const float4*)&A[(size_t)(brow + lr + i * 64) * K + lc * 4];
        pb[i] = *(const float4*)&B[(size_t)(bcol + lr + i * 64) * K + lc * 4];
    }

    for (int k0 = 0; k0 < K; k0 += BK) {
        // stash prefetched tile into smem (transposed)
        #pragma unroll
        for (int i = 0; i < 2; ++i) {
            int r = lr + i * 64;
            As[lc * 4 + 0][r] = pa[i].x; As[lc * 4 + 1][r] = pa[i].y;
            As[lc * 4 + 2][r] = pa[i].z; As[lc * 4 + 3][r] = pa[i].w;
            Bs[lc * 4 + 0][r] = pb[i].x; Bs[lc * 4 + 1][r] = pb[i].y;
            Bs[lc * 4 + 2][r] = pb[i].z; Bs[lc * 4 + 3][r] = pb[i].w;
        }
        __syncthreads();

        // issue next tile's global loads early, overlapping with compute
        if (k0 + BK < K) {
            #pragma unroll
            for (int i = 0; i < 2; ++i) {
                pa[i] = *(const float4*)&A[(size_t)(brow + lr + i * 64) * K + k0 + BK + lc * 4];
                pb[i] = *(const float4*)&B[(size_t)(bcol + lr + i * 64) * K + k0 + BK + lc * 4];
            }
        }

        #pragma unroll
        for (int kk = 0; kk < BK; ++kk) {
            float a[8], b[8];
            *(float4*)&a[0] = *(const float4*)&As[kk][ty * 8];
            *(float4*)&a[4] = *(const float4*)&As[kk][ty * 8 + 4];
            *(float4*)&b[0] = *(const float4*)&Bs[kk][tx * 8];
            *(float4*)&b[4] = *(const float4*)&Bs[kk][tx * 8 + 4];
            #pragma unroll
            for (int i = 0; i < 8; ++i)
                #pragma unroll
                for (int j = 0; j < 8; ++j) acc[i][j] += a[i] * b[j];
        }
        __syncthreads();
    }

    #pragma unroll
    for (int i = 0; i < 8; ++i) {
        int row = brow + ty * 8 + i;
        #pragma unroll
        for (int j = 0; j < 8; j += 4) {
            int col = bcol + tx * 8 + j;
            float4 o;
            o.x = acc[i][j + 0] + bias[col + 0];
            o.y = acc[i][j + 1] + bias[col + 1];
            o.z = acc[i][j + 2] + bias[col + 2];
            o.w = acc[i][j + 3] + bias[col + 3];
            if (RELU) {
                o.x = fmaxf(o.x, 0.0f); o.y = fmaxf(o.y, 0.0f);
                o.z = fmaxf(o.z, 0.0f); o.w = fmaxf(o.w, 0.0f);
            }
            *(float4*)&C[(size_t)row * N + col] = o;
        }
    }
}

// ---------------- kernel 4: gather + multi-head attention (warp per node) ------
// score(n,l) = q.Kh[u_l] + q.Ke[e_l]; the Ke term only depends on the edge, so
// it is computed once per edge (4x) instead of once per key slot (32x).
__global__ __launch_bounds__(256)
void attn_kernel(const int* __restrict__ node_edges, const int* __restrict__ edge_nodes,
                 const float* __restrict__ bv) {
    __shared__ float s_attn[8][8][33];   // [warp][head][l], padded vs bank conflicts
    const unsigned FULL = 0xffffffffu;
    const int warp = threadIdx.x >> 5;
    const int lane = threadIdx.x & 31;
    const int n = blockIdx.x * 8 + warp;

    // per-lane slice of q: dims 4*lane .. 4*lane+3  (head = lane>>2)
    float4 q4 = *(const float4*)&g_QKV[(size_t)n * 384 + lane * 4];

    // edges of this node; lane d (0..3) holds e[d]
    int e_mine = node_edges[n * DEG + (lane & 3)];
    // key slot for THIS lane: l = lane, d = lane>>3, k = lane&7
    int e_l = __shfl_sync(FULL, e_mine, lane >> 3);
    int u   = edge_nodes[e_l * EK + (lane & 7)];

    // ---- phase 0: per-edge bias term  se[d] = q_h . Ke[e_d]_h  (all lanes of a
    // head end up holding it after the xor-reduction)
    float se[DEG];
    #pragma unroll
    for (int d = 0; d < DEG; ++d) {
        int ee = __shfl_sync(FULL, e_mine, d);
        float4 ke = *(const float4*)&g_Ke[(size_t)ee * 128 + lane * 4];
        float p = q4.x * ke.x + q4.y * ke.y + q4.z * ke.z + q4.w * ke.w;
        p += __shfl_xor_sync(FULL, p, 1);
        p += __shfl_xor_sync(FULL, p, 2);
        se[d] = p;
    }

    // ---- phase 1: scores[h][l] = (q_h . Kh[u_l]_h + se[l>>3]) * 0.25
    #pragma unroll
    for (int l = 0; l < L_KEYS; ++l) {
        int uu = __shfl_sync(FULL, u, l);
        float4 kv = *(const float4*)&g_QKV[(size_t)uu * 384 + 128 + lane * 4];
        float p = q4.x * kv.x + q4.y * kv.y + q4.z * kv.z + q4.w * kv.w;
        p += __shfl_xor_sync(FULL, p, 1);
        p += __shfl_xor_sync(FULL, p, 2);
        if ((lane & 3) == 0)
            s_attn[warp][lane >> 2][l] = (p + se[l >> 3]) * 0.25f;  // 1/sqrt(16)
    }
    __syncwarp();

    // ---- phase 2: softmax over L per head, parallel across all 32 lanes.
    // lane covers head h = lane>>2, key quarter qtr = lane&3 -> l = qtr*8..qtr*8+7
    {
        const int h = lane >> 2;
        const int base = (lane & 3) * 8;
        float ex[8];
        float m = -INFINITY;
        #pragma unroll
        for (int j = 0; j < 8; ++j) m = fmaxf(m, s_attn[warp][h][base + j]);
        m = fmaxf(m, __shfl_xor_sync(FULL, m, 1));
        m = fmaxf(m, __shfl_xor_sync(FULL, m, 2));
        float s = 0.0f;
        #pragma unroll
        for (int j = 0; j < 8; ++j) {
            ex[j] = __expf(s_attn[warp][h][base + j] - m);
            s += ex[j];
        }
        s += __shfl_xor_sync(FULL, s, 1);
        s += __shfl_xor_sync(FULL, s, 2);
        float inv = 1.0f / s;
        #pragma unroll
        for (int j = 0; j < 8; ++j) s_attn[warp][h][base + j] = ex[j] * inv;
    }
    __syncwarp();

    // ---- phase 3: ctx = sum_l attn[h][l] * Vh[u_l]  (+ bv, since sum attn = 1)
    float4 acc = make_float4(0.f, 0.f, 0.f, 0.f);
    const int h = lane >> 2;
    #pragma unroll
    for (int l = 0; l < L_KEYS; ++l) {
        int uu = __shfl_sync(FULL, u, l);
        float a = s_attn[warp][h][l];
        float4 vv = *(const float4*)&g_QKV[(size_t)uu * 384 + 256 + lane * 4];
        acc.x += a * vv.x; acc.y += a * vv.y;
        acc.z += a * vv.z; acc.w += a * vv.w;
    }
    float4 b4 = *(const float4*)&bv[lane * 4];
    acc.x += b4.x; acc.y += b4.y; acc.z += b4.z; acc.w += b4.w;
    *(float4*)&g_ctx[(size_t)n * 128 + lane * 4] = acc;
}

// ---------------- launch --------------------------------------------------------
extern "C" void kernel_launch(void* const* d_in, const int* in_sizes, int n_in,
                              void* d_out, int out_size) {
    const float* x          = (const float*)d_in[0];
    const float* edge_attr  = (const float*)d_in[1];
    const int*   node_edges = (const int*)  d_in[2];
    const int*   edge_nodes = (const int*)  d_in[3];
    const float* W_lin      = (const float*)d_in[4];
    const float* W_edge     = (const float*)d_in[5];
    const float* Wq         = (const float*)d_in[6];
    const float* Wk         = (const float*)d_in[7];
    const float* Wv         = (const float*)d_in[8];
    const float* bq         = (const float*)d_in[9];
    const float* bk         = (const float*)d_in[10];
    const float* bv         = (const float*)d_in[11];
    const float* Wo         = (const float*)d_in[12];
    const float* bo         = (const float*)d_in[13];
    float* out = (float*)d_out;

    float *pWcat, *pWkE, *pbias, *pQKV, *pKe, *pctx;
    cudaGetSymbolAddress((void**)&pWcat, g_Wcat);
    cudaGetSymbolAddress((void**)&pWkE,  g_WkE);
    cudaGetSymbolAddress((void**)&pbias, g_bias_cat);
    cudaGetSymbolAddress((void**)&pQKV,  g_QKV);
    cudaGetSymbolAddress((void**)&pKe,   g_Ke);
    cudaGetSymbolAddress((void**)&pctx,  g_ctx);

    // 1) fuse weights: Wcat = [Wq;Wk;Wv] @ W_lin ; WkE = Wk @ W_edge ; bias_cat
    prep_kernel<<<224, 256>>>(W_lin, W_edge, Wq, Wk, Wv, bq);

    // 2) QKV = x @ Wcat^T + [bq|0|0]      [32768, 384]
    sgemm_nt<false><<<dim3(N_NODES / 128, 3), 256>>>(x, pWcat, pbias, pQKV,
                                                     N_NODES, 384, IN_DIM);

    // 3) Ke = edge_attr @ WkE^T + bk      [16384, 128]
    sgemm_nt<false><<<dim3(N_EDGES / 128, 1), 256>>>(edge_attr, pWkE, bk, pKe,
                                                     N_EDGES, 128, EDGE_DIM);

    // 4) gather + attention -> ctx        [32768, 128]
    attn_kernel<<<N_NODES / 8, 256>>>(node_edges, edge_nodes, bv);

    // 5) out = relu(ctx @ Wo^T + bo)      [32768, 128]
    sgemm_nt<true><<<dim3(N_NODES / 128, 1), 256>>>(pctx, Wo, bo, out,
                                                    N_NODES, OUT_DIM, OUT_DIM);
}